// round 16
// baseline (speedup 1.0000x reference)
#include <cuda_runtime.h>
#include <cuda_bf16.h>
#include <cstdint>

// Batched complex QR (Q only), LAPACK Householder convention.
//   Input : x [B, 64, 16, 2] float32   Output: q [B, 64, 16, 2] float32
//
// ONE matrix per 32-lane warp. lane = (cg = lane>>3, rl = lane&7):
//   owns rows {rl+8t} x interleaved cols {cg+4u}.
// Reflector in UNNORMALIZED form (identical to clarfg):
//   u = x - beta*e_j,  H a = a - c*u*(u^H a),  c = conj(tau)/|alpha-beta|^2
// NEW: column-norm downdate (xGEQP3 trick): ss_j = nn[col j] maintained by
//   nn_k -= |R[j,k]|^2 each step -> ss needs ONE shfl, so the scalar chain
//   (rsqrt/fdiv) overlaps the m-butterfly instead of serializing after it.
// Phase 2: dual accumulation chains (even/odd i) halve the dependent-FMA chain.

typedef unsigned long long u64;
#define NR    16
#define WPB   4                        // warps (= matrices) per block
#define ROWF2 17                       // padded row stride in float2
#define SXPM  (64 * ROWF2)
#define SRPM  136
#define SMEM_BYTES (WPB * (SXPM + SRPM) * (int)sizeof(float2))   // 39168
#define FULLM 0xffffffffu

__device__ __forceinline__ u64 PK(float lo, float hi) {
    u64 r; asm("mov.b64 %0,{%1,%2};" : "=l"(r) : "f"(lo), "f"(hi)); return r;
}
__device__ __forceinline__ void UPK(u64 v, float& lo, float& hi) {
    asm("mov.b64 {%0,%1},%2;" : "=f"(lo), "=f"(hi) : "l"(v));
}
__device__ __forceinline__ u64 DUP(float x) { return PK(x, x); }
__device__ __forceinline__ u64 SW(u64 z) {
    float a, b; UPK(z, a, b); return PK(b, a);
}
__device__ __forceinline__ u64 FMA2(u64 a, u64 b, u64 c) {
    u64 d; asm("fma.rn.f32x2 %0,%1,%2,%3;" : "=l"(d) : "l"(a), "l"(b), "l"(c)); return d;
}
__device__ __forceinline__ u64 MUL2(u64 a, u64 b) {
    u64 d; asm("mul.rn.f32x2 %0,%1,%2;" : "=l"(d) : "l"(a), "l"(b)); return d;
}
__device__ __forceinline__ u64 ADD2(u64 a, u64 b) {
    u64 d; asm("add.rn.f32x2 %0,%1,%2;" : "=l"(d) : "l"(a), "l"(b)); return d;
}
__device__ __forceinline__ u64 SHX2(u64 v, int s) {
    float a, b; UPK(v, a, b);
    a = __shfl_xor_sync(FULLM, a, s);
    b = __shfl_xor_sync(FULLM, b, s);
    return PK(a, b);
}
__device__ __forceinline__ u64 SHI2(u64 v, int src) {
    float a, b; UPK(v, a, b);
    a = __shfl_sync(FULLM, a, src);
    b = __shfl_sync(FULLM, b, src);
    return PK(a, b);
}

__global__ void __launch_bounds__(128, 4)
qr_householder_kernel(const float* __restrict__ in,
                      float* __restrict__ out,
                      int B)
{
    extern __shared__ float2 smem[];
    const int tid  = threadIdx.x;
    const int warp = tid >> 5;
    const int lane = tid & 31;
    const int cg   = lane >> 3;     // column group: owns cols cg+4u
    const int rl   = lane & 7;      // row lane:     owns rows rl+8t
    const long long b = (long long)blockIdx.x * WPB + warp;
    if (b >= B) return;

    float2* sxm = smem + warp * (SXPM + SRPM);
    float2* sRm = sxm + SXPM;

    // ---- coalesced load -> padded SMEM ----
    {
        const float4* src = (const float4*)(in + b * 2048);
#pragma unroll
        for (int it = 0; it < 16; it++) {
            const int idx = it * 32 + lane;
            const float4 v = src[idx];
            const int row = idx >> 3, cp = idx & 7;
            sxm[row * ROWF2 + 2 * cp]     = make_float2(v.x, v.y);
            sxm[row * ROWF2 + 2 * cp + 1] = make_float2(v.z, v.w);
        }
    }
    __syncwarp();

    // ---- register fill: A[t][u] = (row rl+8t, col cg+4u), packed (re,im) ----
    u64 A[8][4];
#pragma unroll
    for (int t = 0; t < 8; t++)
#pragma unroll
        for (int u = 0; u < 4; u++) {
            const float2 c = sxm[(rl + 8 * t) * ROWF2 + (cg + 4 * u)];
            A[t][u] = PK(c.x, c.y);
        }

    // ---- column-norm init: nn[u] = ||col cg+4u||^2 (all 64 rows) ----
    float nn[4];
    {
        float n0 = 0.f, n1 = 0.f, n2 = 0.f, n3 = 0.f;
#pragma unroll
        for (int t = 0; t < 8; t++) {
            float r_, i_;
            UPK(A[t][0], r_, i_); n0 = fmaf(r_, r_, fmaf(i_, i_, n0));
            UPK(A[t][1], r_, i_); n1 = fmaf(r_, r_, fmaf(i_, i_, n1));
            UPK(A[t][2], r_, i_); n2 = fmaf(r_, r_, fmaf(i_, i_, n2));
            UPK(A[t][3], r_, i_); n3 = fmaf(r_, r_, fmaf(i_, i_, n3));
        }
        u64 p01 = PK(n0, n1), p23 = PK(n2, n3);
#pragma unroll
        for (int s = 4; s; s >>= 1) {
            p01 = ADD2(p01, SHX2(p01, s));
            p23 = ADD2(p23, SHX2(p23, s));
        }
        UPK(p01, nn[0], nn[1]);
        UPK(p23, nn[2], nn[3]);
    }

    // ---- prologue: broadcast column 0 (slot 0, group 0) ----
    u64 xb[8];
#pragma unroll
    for (int t = 0; t < 8; t++)
        xb[t] = SHI2(A[t][0], rl);          // src lane = (0<<3)|rl

    // ================= Householder elimination (cgeqrf) =================
#pragma unroll
    for (int j = 0; j < NR; j++) {
        const int uj = j >> 2, cgj = j & 3, tj = j >> 3, rlj = j & 7;

        // alpha = x[row j]; ss = remaining-rows norm^2 of col j (downdated)
        float alr, ali;
        { u64 al = SHI2(xb[tj], rlj); UPK(al, alr, ali); }
        const float ss = __shfl_sync(FULLM, nn[uj], (cgj << 3) | rl);

        // zero the strictly-above-pivot rows in slot tj (pivot keeps alpha)
        if (rl < rlj) xb[tj] = 0ull;

        // FULL-column dots m[u] = sum_{i>=j} conj(x_i)*a_ik (no norm here)
        u64 P[4], Q[4];
#pragma unroll
        for (int u = 0; u < 4; u++)
            if (4 * u + 3 > j) { P[u] = 0ull; Q[u] = 0ull; }
#pragma unroll
        for (int t = tj; t < 8; t++) {
            float xr, xi; UPK(xb[t], xr, xi);
            const u64 XR = DUP(xr), XI = DUP(xi);
#pragma unroll
            for (int u = 0; u < 4; u++)
                if (4 * u + 3 > j) {
                    P[u] = FMA2(XR, A[t][u], P[u]);
                    Q[u] = FMA2(XI, A[t][u], Q[u]);
                }
        }
        // combine: m = (P.lo + Q.hi, P.hi - Q.lo)
        u64 m[4];
#pragma unroll
        for (int u = 0; u < 4; u++)
            if (4 * u + 3 > j) {
                float pr, pi, qr, qi;
                UPK(P[u], pr, pi); UPK(Q[u], qr, qi);
                m[u] = PK(pr + qi, pi - qr);
            }
        // 3-round butterfly within the 8-lane row group (m only)
#pragma unroll
        for (int s = 4; s; s >>= 1) {
#pragma unroll
            for (int u = 0; u < 4; u++)
                if (4 * u + 3 > j)
                    m[u] = ADD2(m[u], SHX2(m[u], s));
        }

        // scalars (LAPACK clarfg convention) — runs parallel with butterfly
        float bet, ib, ccr, cci, dr, di;
        const float chk = fmaf(alr, alr, ali * ali);
        if (ss <= chk && ali == 0.f) {       // tail ~zero -> tau = 0
            bet = alr; ib = __fdividef(1.f, alr);
            ccr = 0.f; cci = 0.f; dr = 0.f; di = 0.f;
        } else {
            const float rn  = rsqrtf(ss);
            const float sgn = (alr >= 0.f) ? 1.f : -1.f;
            bet = -sgn * (ss * rn);
            ib  = -sgn * rn;                          // 1/beta
            dr = alr - bet; di = ali;
            const float dd = __fdividef(1.f, fmaf(dr, dr, di * di));
            const float f  = ib * dd;
            ccr = (bet - alr) * f;                    // c = conj(tau)/|a-b|^2
            cci = ali * f;
        }
        const u64 CCR = DUP(ccr), CCS = PK(-cci, cci);
        const u64 NB  = DUP(-bet);
        const u64 VP  = PK(dr, di), SVP = PK(di, dr);

        // pivot entry of u is (alpha - beta)
        if (rl == rlj) xb[tj] = VP;

        // per active column: uh = m - beta*ajk, g = c*uh;
        // also R[j,col] and the norm downdate nn -= |R[j,col]|^2
        u64 NG[4], GS[4];
#pragma unroll
        for (int u = 0; u < 4; u++)
            if (4 * u + 3 > j) {
                const u64 ajk = SHI2(A[tj][u], (cg << 3) | rlj);
                const u64 uh  = FMA2(NB, ajk, m[u]);
                const u64 g   = FMA2(CCR, uh, MUL2(CCS, SW(uh)));
                float gr, gi; UPK(g, gr, gi);
                NG[u] = DUP(-gr);
                GS[u] = PK(gi, -gi);    // -g*u = NG*u + GS*SW(u)
                // R row j entry for this column (post-update pivot row)
                const u64 rj = FMA2(NG[u], VP, FMA2(GS[u], SVP, ajk));
                float rr, ri2; UPK(rj, rr, ri2);
                nn[u] = fmaf(-rr, rr, fmaf(-ri2, ri2, nn[u]));
            }

        // next-step broadcast parameters
        const int ujn   = (j + 1) >> 2;
        const int srcvn = (((j + 1) & 3) << 3) | rl;

        // rank-1 update per row-block t, then issue next pivot broadcast
#pragma unroll
        for (int t = tj; t < 8; t++) {
            const u64 v = xb[t], sv = SW(v);
#pragma unroll
            for (int u = 0; u < 4; u++)
                if (4 * u + 3 > j) {
                    if (4 * u > j || (cg + 4 * u > j))
                        A[t][u] = FMA2(NG[u], v, FMA2(GS[u], sv, A[t][u]));
                }
            if (j < NR - 1)
                xb[t] = SHI2(A[t][ujn], srcvn);
        }
        // R diagonal slot stores 1/beta (real)
        if (cg == cgj && rl == rlj) A[tj][uj] = PK(ib, 0.f);
    }

    // ---- publish R (packed upper triangle; diag slot = 1/beta) ----
#pragma unroll
    for (int u = 0; u < 4; u++) {
        const int col = cg + 4 * u;
#pragma unroll
        for (int t = 0; t < 2; t++) {      // rows 0..15 live in t=0,1
            const int i = rl + 8 * t;
            if (i <= col) {
                float rr, ri; UPK(A[t][u], rr, ri);
                sRm[(col * (col + 1)) / 2 + i] = make_float2(rr, ri);
            }
        }
    }
    __syncwarp();

    // ========== Q = X * R^{-1} back-substitution (rows lane, lane+32) ==========
    // Separated planes; dual accumulation chains (even/odd i).
    u64 qr[NR], qi[NR];
#pragma unroll
    for (int k = 0; k < NR; k++) {
        const float2 y0 = sxm[lane * ROWF2 + k];
        const float2 y1 = sxm[(lane + 32) * ROWF2 + k];
        u64 yrA = PK(y0.x, y1.x), yiA = PK(y0.y, y1.y);
        u64 yrB = 0ull, yiB = 0ull;
#pragma unroll
        for (int i = 0; i < k; i++) {
            const float2 rc = sRm[(k * (k + 1)) / 2 + i];   // R[i][k]
            const u64 NRR = DUP(-rc.x), RID = DUP(rc.y), NRI = DUP(-rc.y);
            if ((i & 1) == 0) {
                yrA = FMA2(NRR, qr[i], FMA2(RID, qi[i], yrA));
                yiA = FMA2(NRR, qi[i], FMA2(NRI, qr[i], yiA));
            } else {
                yrB = FMA2(NRR, qr[i], FMA2(RID, qi[i], yrB));
                yiB = FMA2(NRR, qi[i], FMA2(NRI, qr[i], yiB));
            }
        }
        const u64 IB = DUP(sRm[(k * (k + 1)) / 2 + k].x);   // 1/beta_k
        qr[k] = MUL2(ADD2(yrA, yrB), IB);
        qi[k] = MUL2(ADD2(yiA, yiB), IB);
    }

    // ---- stage Q back into sx (this lane's own rows only) ----
#pragma unroll
    for (int k = 0; k < NR; k++) {
        float r0, r1, i0, i1;
        UPK(qr[k], r0, r1); UPK(qi[k], i0, i1);
        sxm[lane * ROWF2 + k]        = make_float2(r0, i0);
        sxm[(lane + 32) * ROWF2 + k] = make_float2(r1, i1);
    }
    __syncwarp();

    // ---- coalesced store ----
    {
        float4* dst = (float4*)(out + b * 2048);
#pragma unroll
        for (int it = 0; it < 16; it++) {
            const int idx = it * 32 + lane;
            const int row = idx >> 3, cp = idx & 7;
            const float2 v0 = sxm[row * ROWF2 + 2 * cp];
            const float2 v1 = sxm[row * ROWF2 + 2 * cp + 1];
            dst[idx] = make_float4(v0.x, v0.y, v1.x, v1.y);
        }
    }
}

extern "C" void kernel_launch(void* const* d_in, const int* in_sizes, int n_in,
                              void* d_out, int out_size)
{
    const float* x = (const float*)d_in[0];
    float* q = (float*)d_out;
    const int B = in_sizes[0] / (64 * NR * 2);   // 32768

    cudaFuncSetAttribute(qr_householder_kernel,
                         cudaFuncAttributeMaxDynamicSharedMemorySize,
                         SMEM_BYTES);

    const int grid = (B + WPB - 1) / WPB;
    qr_householder_kernel<<<grid, WPB * 32, SMEM_BYTES>>>(x, q, B);
}

// round 17
// speedup vs baseline: 1.0739x; 1.0739x over previous
#include <cuda_runtime.h>
#include <cuda_bf16.h>
#include <cstdint>

// Batched complex QR (Q only), LAPACK Householder convention.
//   Input : x [B, 64, 16, 2] float32   Output: q [B, 64, 16, 2] float32
//
// ONE matrix per 32-lane warp. lane = (cg = lane>>3, rl = lane&7):
//   owns rows {rl+8t} x interleaved cols {cg+4u}.
// Reflector in UNNORMALIZED form (identical to clarfg):
//   u = x - beta*e_j,  H a = a - c*u*(u^H a),  c = conj(tau)/|alpha-beta|^2
//   u^H a_k = m_k - beta*a_jk,  m_k = full-column dot (pivot included)
// R diagonal slot stores 1/beta. Phase 2 separated re/im planes, dual
// accumulation chains. Pipelined: next pivot column broadcast AND next
// alpha extraction both issue inside the current step's update loop.

typedef unsigned long long u64;
#define NR    16
#define WPB   4                        // warps (= matrices) per block
#define ROWF2 17                       // padded row stride in float2
#define SXPM  (64 * ROWF2)
#define SRPM  136
#define SMEM_BYTES (WPB * (SXPM + SRPM) * (int)sizeof(float2))   // 39168
#define FULLM 0xffffffffu

__device__ __forceinline__ u64 PK(float lo, float hi) {
    u64 r; asm("mov.b64 %0,{%1,%2};" : "=l"(r) : "f"(lo), "f"(hi)); return r;
}
__device__ __forceinline__ void UPK(u64 v, float& lo, float& hi) {
    asm("mov.b64 {%0,%1},%2;" : "=f"(lo), "=f"(hi) : "l"(v));
}
__device__ __forceinline__ u64 DUP(float x) { return PK(x, x); }
__device__ __forceinline__ u64 SW(u64 z) {
    float a, b; UPK(z, a, b); return PK(b, a);
}
__device__ __forceinline__ u64 FMA2(u64 a, u64 b, u64 c) {
    u64 d; asm("fma.rn.f32x2 %0,%1,%2,%3;" : "=l"(d) : "l"(a), "l"(b), "l"(c)); return d;
}
__device__ __forceinline__ u64 MUL2(u64 a, u64 b) {
    u64 d; asm("mul.rn.f32x2 %0,%1,%2;" : "=l"(d) : "l"(a), "l"(b)); return d;
}
__device__ __forceinline__ u64 ADD2(u64 a, u64 b) {
    u64 d; asm("add.rn.f32x2 %0,%1,%2;" : "=l"(d) : "l"(a), "l"(b)); return d;
}
__device__ __forceinline__ u64 SHX2(u64 v, int s) {
    float a, b; UPK(v, a, b);
    a = __shfl_xor_sync(FULLM, a, s);
    b = __shfl_xor_sync(FULLM, b, s);
    return PK(a, b);
}
__device__ __forceinline__ u64 SHI2(u64 v, int src) {
    float a, b; UPK(v, a, b);
    a = __shfl_sync(FULLM, a, src);
    b = __shfl_sync(FULLM, b, src);
    return PK(a, b);
}

__global__ void __launch_bounds__(128, 4)
qr_householder_kernel(const float* __restrict__ in,
                      float* __restrict__ out,
                      int B)
{
    extern __shared__ float2 smem[];
    const int tid  = threadIdx.x;
    const int warp = tid >> 5;
    const int lane = tid & 31;
    const int cg   = lane >> 3;     // column group: owns cols cg+4u
    const int rl   = lane & 7;      // row lane:     owns rows rl+8t
    const long long b = (long long)blockIdx.x * WPB + warp;
    if (b >= B) return;

    float2* sxm = smem + warp * (SXPM + SRPM);
    float2* sRm = sxm + SXPM;

    // ---- coalesced load -> padded SMEM ----
    {
        const float4* src = (const float4*)(in + b * 2048);
#pragma unroll
        for (int it = 0; it < 16; it++) {
            const int idx = it * 32 + lane;
            const float4 v = src[idx];
            const int row = idx >> 3, cp = idx & 7;
            sxm[row * ROWF2 + 2 * cp]     = make_float2(v.x, v.y);
            sxm[row * ROWF2 + 2 * cp + 1] = make_float2(v.z, v.w);
        }
    }
    __syncwarp();

    // ---- register fill: A[t][u] = (row rl+8t, col cg+4u), packed (re,im) ----
    u64 A[8][4];
#pragma unroll
    for (int t = 0; t < 8; t++)
#pragma unroll
        for (int u = 0; u < 4; u++) {
            const float2 c = sxm[(rl + 8 * t) * ROWF2 + (cg + 4 * u)];
            A[t][u] = PK(c.x, c.y);
        }

    // ---- prologue: broadcast column 0 and alpha_0 ----
    u64 xb[8];
#pragma unroll
    for (int t = 0; t < 8; t++)
        xb[t] = SHI2(A[t][0], rl);          // src lane = (0<<3)|rl
    u64 alj = SHI2(xb[0], 0);               // alpha for j = 0

    // ================= Householder elimination (cgeqrf) =================
#pragma unroll
    for (int j = 0; j < NR; j++) {
        const int uj = j >> 2, cgj = j & 3, tj = j >> 3, rlj = j & 7;

        // alpha = x[row j] (pre-broadcast in previous step's shadow)
        float alr, ali;
        UPK(alj, alr, ali);

        // zero the strictly-above-pivot rows in slot tj (pivot keeps alpha)
        if (rl < rlj) xb[tj] = 0ull;

        // FULL-column dots m[u] = sum_{i>=j} conj(x_i)*a_ik  and ss = ||x||^2
        float ss = 0.f;
        u64 P[4], Q[4];
#pragma unroll
        for (int u = 0; u < 4; u++)
            if (4 * u + 3 > j) { P[u] = 0ull; Q[u] = 0ull; }
#pragma unroll
        for (int t = tj; t < 8; t++) {
            float xr, xi; UPK(xb[t], xr, xi);
            ss = fmaf(xr, xr, fmaf(xi, xi, ss));
            const u64 XR = DUP(xr), XI = DUP(xi);
#pragma unroll
            for (int u = 0; u < 4; u++)
                if (4 * u + 3 > j) {
                    P[u] = FMA2(XR, A[t][u], P[u]);
                    Q[u] = FMA2(XI, A[t][u], Q[u]);
                }
        }
        // combine: m = (P.lo + Q.hi, P.hi - Q.lo)
        u64 m[4];
#pragma unroll
        for (int u = 0; u < 4; u++)
            if (4 * u + 3 > j) {
                float pr, pi, qr, qi;
                UPK(P[u], pr, pi); UPK(Q[u], qr, qi);
                m[u] = PK(pr + qi, pi - qr);
            }
        // 3-round butterfly within the 8-lane row group
#pragma unroll
        for (int s = 4; s; s >>= 1) {
            ss += __shfl_xor_sync(FULLM, ss, s);
#pragma unroll
            for (int u = 0; u < 4; u++)
                if (4 * u + 3 > j)
                    m[u] = ADD2(m[u], SHX2(m[u], s));
        }

        // scalars (exact LAPACK clarfg convention); ib = 1/beta kept for Q
        float bet, ib, ccr, cci, dr, di;
        const float chk = fmaf(alr, alr, ali * ali);
        if (ss == chk && ali == 0.f) {       // tail exactly zero -> tau = 0
            bet = alr; ib = __fdividef(1.f, alr);
            ccr = 0.f; cci = 0.f; dr = 0.f; di = 0.f;
        } else {
            const float rn  = rsqrtf(ss);
            const float sgn = (alr >= 0.f) ? 1.f : -1.f;
            bet = -sgn * (ss * rn);
            ib  = -sgn * rn;                          // 1/beta
            dr = alr - bet; di = ali;
            const float dd = __fdividef(1.f, fmaf(dr, dr, di * di));
            const float f  = ib * dd;
            ccr = (bet - alr) * f;                    // c = conj(tau)/|a-b|^2
            cci = ali * f;
        }
        const u64 CCR = DUP(ccr), CCS = PK(-cci, cci);
        const u64 NB  = DUP(-bet);

        // pivot entry of u is (alpha - beta)
        if (rl == rlj) xb[tj] = PK(dr, di);

        // per active column: uh = m - beta*ajk, g = c*uh
        u64 NG[4], GS[4];
#pragma unroll
        for (int u = 0; u < 4; u++)
            if (4 * u + 3 > j) {
                const u64 ajk = SHI2(A[tj][u], (cg << 3) | rlj);
                const u64 uh  = FMA2(NB, ajk, m[u]);
                const u64 g   = FMA2(CCR, uh, MUL2(CCS, SW(uh)));
                float gr, gi; UPK(g, gr, gi);
                NG[u] = DUP(-gr);
                GS[u] = PK(gi, -gi);    // -g*u = NG*u + GS*SW(u)
            }

        // next-step broadcast parameters
        const int ujn   = (j + 1) >> 2;
        const int tjn   = (j + 1) >> 3;
        const int rljn  = (j + 1) & 7;
        const int srcvn = (((j + 1) & 3) << 3) | rl;

        // rank-1 update per row-block t, then issue next pivot broadcast
#pragma unroll
        for (int t = tj; t < 8; t++) {
            const u64 v = xb[t], sv = SW(v);
#pragma unroll
            for (int u = 0; u < 4; u++)
                if (4 * u + 3 > j) {
                    if (4 * u > j || (cg + 4 * u > j))
                        A[t][u] = FMA2(NG[u], v, FMA2(GS[u], sv, A[t][u]));
                }
            if (j < NR - 1)
                xb[t] = SHI2(A[t][ujn], srcvn);
        }
        // pre-broadcast next alpha (hides under nothing serial: issued as
        // soon as xb[tjn] lands, consumed next iteration)
        if (j < NR - 1)
            alj = SHI2(xb[tjn], rljn);

        // R diagonal slot stores 1/beta (real)
        if (cg == cgj && rl == rlj) A[tj][uj] = PK(ib, 0.f);
    }

    // ---- publish R (packed upper triangle; diag slot = 1/beta) ----
#pragma unroll
    for (int u = 0; u < 4; u++) {
        const int col = cg + 4 * u;
#pragma unroll
        for (int t = 0; t < 2; t++) {      // rows 0..15 live in t=0,1
            const int i = rl + 8 * t;
            if (i <= col) {
                float rr, ri; UPK(A[t][u], rr, ri);
                sRm[(col * (col + 1)) / 2 + i] = make_float2(rr, ri);
            }
        }
    }
    __syncwarp();

    // ========== Q = X * R^{-1} back-substitution (rows lane, lane+32) ==========
    // Separated planes; dual accumulation chains (even/odd i).
    u64 qr[NR], qi[NR];
#pragma unroll
    for (int k = 0; k < NR; k++) {
        const float2 y0 = sxm[lane * ROWF2 + k];
        const float2 y1 = sxm[(lane + 32) * ROWF2 + k];
        u64 yrA = PK(y0.x, y1.x), yiA = PK(y0.y, y1.y);
        u64 yrB = 0ull, yiB = 0ull;
#pragma unroll
        for (int i = 0; i < k; i++) {
            const float2 rc = sRm[(k * (k + 1)) / 2 + i];   // R[i][k]
            const u64 NRR = DUP(-rc.x), RID = DUP(rc.y), NRI = DUP(-rc.y);
            if ((i & 1) == 0) {
                yrA = FMA2(NRR, qr[i], FMA2(RID, qi[i], yrA));
                yiA = FMA2(NRR, qi[i], FMA2(NRI, qr[i], yiA));
            } else {
                yrB = FMA2(NRR, qr[i], FMA2(RID, qi[i], yrB));
                yiB = FMA2(NRR, qi[i], FMA2(NRI, qr[i], yiB));
            }
        }
        const u64 IB = DUP(sRm[(k * (k + 1)) / 2 + k].x);   // 1/beta_k
        qr[k] = MUL2(ADD2(yrA, yrB), IB);
        qi[k] = MUL2(ADD2(yiA, yiB), IB);
    }

    // ---- stage Q back into sx (this lane's own rows only) ----
#pragma unroll
    for (int k = 0; k < NR; k++) {
        float r0, r1, i0, i1;
        UPK(qr[k], r0, r1); UPK(qi[k], i0, i1);
        sxm[lane * ROWF2 + k]        = make_float2(r0, i0);
        sxm[(lane + 32) * ROWF2 + k] = make_float2(r1, i1);
    }
    __syncwarp();

    // ---- coalesced store ----
    {
        float4* dst = (float4*)(out + b * 2048);
#pragma unroll
        for (int it = 0; it < 16; it++) {
            const int idx = it * 32 + lane;
            const int row = idx >> 3, cp = idx & 7;
            const float2 v0 = sxm[row * ROWF2 + 2 * cp];
            const float2 v1 = sxm[row * ROWF2 + 2 * cp + 1];
            dst[idx] = make_float4(v0.x, v0.y, v1.x, v1.y);
        }
    }
}

extern "C" void kernel_launch(void* const* d_in, const int* in_sizes, int n_in,
                              void* d_out, int out_size)
{
    const float* x = (const float*)d_in[0];
    float* q = (float*)d_out;
    const int B = in_sizes[0] / (64 * NR * 2);   // 32768

    cudaFuncSetAttribute(qr_householder_kernel,
                         cudaFuncAttributeMaxDynamicSharedMemorySize,
                         SMEM_BYTES);

    const int grid = (B + WPB - 1) / WPB;
    qr_householder_kernel<<<grid, WPB * 32, SMEM_BYTES>>>(x, q, B);
}